// round 4
// baseline (speedup 1.0000x reference)
#include <cuda_runtime.h>
#include <cstdint>
#include <cstddef>

#define NP 200000
#define NA 100000
#define EC 4000000
#define EW 2000000

// ---------------- device scratch (allocation-free) ----------------
__device__ float g_xls[(size_t)NP * 64];   // dis-scaled x_paper @ gcn_W
__device__ float g_P  [(size_t)NP * 64];   // paper accumulation
__device__ float g_SA [(size_t)NP * 64];   // sage neighbor mean
__device__ float g_XS [(size_t)NP * 64];   // gat source feats (paper)
__device__ float g_XD [(size_t)NA * 64];   // gat dst feats (author)
__device__ float g_xp1[(size_t)NP * 64];   // x_paper after layer 0
__device__ float g_xa1[(size_t)NA * 64];   // x_author after layer 0/1
__device__ float g_Wcat[128 * 192];        // [gcn_W0 | sage_Wr0 | gat_Ws0]
__device__ float g_dis [NP];
__device__ float g_asrc[NP];
__device__ float g_adst[NA];
__device__ int g_degC[NP], g_degWp[NP], g_degWa[NA];
__device__ int g_offC[NP], g_offWp[NP], g_offWa[NA];
__device__ int g_curC[NP], g_curWp[NP], g_curWa[NA];
__device__ int g_bsum[512];
__device__ int g_csrC[EC], g_csrWp[EW], g_csrWa[EW];

// ---------------- utility kernels ----------------
__global__ void k_count(const int* __restrict__ idx, int* cnt, int E) {
    int i = blockIdx.x * blockDim.x + threadIdx.x;
    if (i < E) atomicAdd(&cnt[idx[i]], 1);
}
__global__ void k_dis(const int* __restrict__ cnt, float* dis, int n) {
    int i = blockIdx.x * blockDim.x + threadIdx.x;
    if (i < n) dis[i] = rsqrtf((float)cnt[i] + 1.0f);
}
__global__ void k_wcat(const float* __restrict__ w0, const float* __restrict__ w1,
                       const float* __restrict__ w2, float* __restrict__ out) {
    int i = blockIdx.x * blockDim.x + threadIdx.x;
    if (i >= 128 * 192) return;
    int k = i / 192, c = i % 192;
    float v = (c < 64) ? w0[k * 64 + c]
            : (c < 128) ? w1[k * 64 + (c - 64)]
            : w2[k * 64 + (c - 128)];
    out[i] = v;
}

// ---------------- scan (3-phase, blocks of 512) ----------------
__global__ void k_scan1(const int* __restrict__ deg, int* off, int* bsum, int n) {
    __shared__ int sh[512];
    int t = threadIdx.x, i = blockIdx.x * 512 + t;
    int v = (i < n) ? deg[i] : 0;
    sh[t] = v; __syncthreads();
    #pragma unroll
    for (int o = 1; o < 512; o <<= 1) {
        int x = (t >= o) ? sh[t - o] : 0;
        __syncthreads(); sh[t] += x; __syncthreads();
    }
    if (i < n) off[i] = sh[t] - v;
    if (t == 511) bsum[blockIdx.x] = sh[511];
}
__global__ void k_scan2(int* bsum, int nb) {
    __shared__ int sh[512];
    int t = threadIdx.x;
    int v = (t < nb) ? bsum[t] : 0;
    sh[t] = v; __syncthreads();
    #pragma unroll
    for (int o = 1; o < 512; o <<= 1) {
        int x = (t >= o) ? sh[t - o] : 0;
        __syncthreads(); sh[t] += x; __syncthreads();
    }
    if (t < nb) bsum[t] = sh[t] - v;
}
__global__ void k_scan3(int* off, int* cur, const int* __restrict__ bsum, int n) {
    int i = blockIdx.x * blockDim.x + threadIdx.x;
    if (i < n) { int v = off[i] + bsum[i >> 9]; off[i] = v; cur[i] = v; }
}
__global__ void k_fill(const int* __restrict__ dst, const int* __restrict__ src,
                       int* cur, int* csr, int E) {
    int i = blockIdx.x * blockDim.x + threadIdx.x;
    if (i < E) {
        int pos = atomicAdd(&cur[dst[i]], 1);
        csr[pos] = src[i];
    }
}

// ---------------- gathers (1 warp / node, 2 cols / lane) ----------------
// P += dis[w] * (sum_{nbr} xls[nbr] + xls[w])    (P holds sage_Wr part)
__global__ void k_gcn_gather(const int* __restrict__ off, const int* __restrict__ csr,
                             const float* __restrict__ xls, const float* __restrict__ dis,
                             float* __restrict__ P, int n, int E) {
    int w = (blockIdx.x * blockDim.x + threadIdx.x) >> 5;
    int lane = threadIdx.x & 31;
    if (w >= n) return;
    int beg = off[w], end = (w == n - 1) ? E : off[w + 1];
    float a0 = 0.f, a1 = 0.f;
    int t = beg;
    for (; t + 4 <= end; t += 4) {
        int s0 = __ldg(&csr[t]),     s1 = __ldg(&csr[t + 1]);
        int s2 = __ldg(&csr[t + 2]), s3 = __ldg(&csr[t + 3]);
        float b0 = xls[s0 * 64 + lane],      c0 = xls[s0 * 64 + 32 + lane];
        float b1 = xls[s1 * 64 + lane],      c1 = xls[s1 * 64 + 32 + lane];
        float b2 = xls[s2 * 64 + lane],      c2 = xls[s2 * 64 + 32 + lane];
        float b3 = xls[s3 * 64 + lane],      c3 = xls[s3 * 64 + 32 + lane];
        a0 += (b0 + b1) + (b2 + b3);
        a1 += (c0 + c1) + (c2 + c3);
    }
    for (; t < end; t++) {
        int s = __ldg(&csr[t]);
        a0 += xls[s * 64 + lane];
        a1 += xls[s * 64 + 32 + lane];
    }
    float dd = dis[w];
    P[(size_t)w * 64 + lane]      += dd * (a0 + xls[w * 64 + lane]);
    P[(size_t)w * 64 + 32 + lane] += dd * (a1 + xls[w * 64 + 32 + lane]);
}

__global__ void k_sage_gather(const int* __restrict__ off, const int* __restrict__ csr,
                              const float* __restrict__ xa, float* __restrict__ SA,
                              int n, int E) {
    int w = (blockIdx.x * blockDim.x + threadIdx.x) >> 5;
    int lane = threadIdx.x & 31;
    if (w >= n) return;
    int beg = off[w], end = (w == n - 1) ? E : off[w + 1];
    float a0 = 0.f, a1 = 0.f;
    int t = beg;
    for (; t + 4 <= end; t += 4) {
        int s0 = __ldg(&csr[t]),     s1 = __ldg(&csr[t + 1]);
        int s2 = __ldg(&csr[t + 2]), s3 = __ldg(&csr[t + 3]);
        float b0 = xa[s0 * 64 + lane],      c0 = xa[s0 * 64 + 32 + lane];
        float b1 = xa[s1 * 64 + lane],      c1 = xa[s1 * 64 + 32 + lane];
        float b2 = xa[s2 * 64 + lane],      c2 = xa[s2 * 64 + 32 + lane];
        float b3 = xa[s3 * 64 + lane],      c3 = xa[s3 * 64 + 32 + lane];
        a0 += (b0 + b1) + (b2 + b3);
        a1 += (c0 + c1) + (c2 + c3);
    }
    for (; t < end; t++) {
        int s = __ldg(&csr[t]);
        a0 += xa[s * 64 + lane];
        a1 += xa[s * 64 + 32 + lane];
    }
    float r = 1.0f / fmaxf((float)(end - beg), 1.0f);
    SA[(size_t)w * 64 + lane]      = a0 * r;
    SA[(size_t)w * 64 + 32 + lane] = a1 * r;
}

// fused GAT: per-author softmax denom + weighted gather + bias + relu
__global__ void k_gat_gather(const int* __restrict__ off, const int* __restrict__ csr,
                             const float* __restrict__ asrc, const float* __restrict__ adst,
                             const float* __restrict__ XS, const float* __restrict__ bias,
                             float* __restrict__ out, int n, int E) {
    int w = (blockIdx.x * blockDim.x + threadIdx.x) >> 5;
    int lane = threadIdx.x & 31;
    if (w >= n) return;
    int beg = off[w], end = (w == n - 1) ? E : off[w + 1];
    float ad = adst[w];
    float den = 0.f, a0 = 0.f, a1 = 0.f;
    int t = beg;
    for (; t + 2 <= end; t += 2) {
        int p0 = __ldg(&csr[t]), p1 = __ldg(&csr[t + 1]);
        float e0 = asrc[p0] + ad; e0 = (e0 > 0.f) ? e0 : 0.2f * e0;
        float e1 = asrc[p1] + ad; e1 = (e1 > 0.f) ? e1 : 0.2f * e1;
        float x0 = __expf(e0), x1 = __expf(e1);
        float b0 = XS[p0 * 64 + lane],      c0 = XS[p0 * 64 + 32 + lane];
        float b1 = XS[p1 * 64 + lane],      c1 = XS[p1 * 64 + 32 + lane];
        den += x0 + x1;
        a0 += x0 * b0 + x1 * b1;
        a1 += x0 * c0 + x1 * c1;
    }
    for (; t < end; t++) {
        int p = __ldg(&csr[t]);
        float e = asrc[p] + ad; e = (e > 0.f) ? e : 0.2f * e;
        float x = __expf(e);
        den += x;
        a0 += x * XS[p * 64 + lane];
        a1 += x * XS[p * 64 + 32 + lane];
    }
    float r = (den > 0.f) ? (1.0f / den) : 0.f;
    float o0 = a0 * r + bias[lane];
    float o1 = a1 * r + bias[lane + 32];
    out[(size_t)w * 64 + lane]      = fmaxf(o0, 0.f);
    out[(size_t)w * 64 + 32 + lane] = fmaxf(o1, 0.f);
}

// out[r] = dot(X[r,:64], v) -- one warp per row
__global__ void k_rowdot(const float* __restrict__ X, const float* __restrict__ v,
                         float* __restrict__ out, int M) {
    int t = blockIdx.x * blockDim.x + threadIdx.x;
    int w = t >> 5, lane = t & 31;
    if (w >= M) return;
    const float* xr = X + (size_t)w * 64;
    float a = xr[lane] * v[lane] + xr[lane + 32] * v[lane + 32];
    #pragma unroll
    for (int o = 16; o > 0; o >>= 1) a += __shfl_xor_sync(0xFFFFFFFFu, a, o);
    if (lane == 0) out[w] = a;
}

// ---------------- 8x16 register-blocked f32x2 GEMM, KC=16 ----------------
// Y[M,N] = X[M,K] @ W[K,N]; mode 0: write, 1: accumulate into Y,
// 2: Y = relu(acc + addsrc + bias + bias2)
template <int K, int N, int MT>
__global__ void __launch_bounds__((MT / 8) * (N / 16)) k_gemmB(
        const float* __restrict__ X, const float* __restrict__ W,
        const float* __restrict__ bias, const float* __restrict__ bias2,
        const float* __restrict__ addsrc, float* __restrict__ Y, int M, int mode) {
    constexpr int NG = N / 16;
    constexpr int T = (MT / 8) * NG;
    constexpr int RG = MT / 8;
    __shared__ __align__(16) float2 Xd[MT * 17];
    __shared__ __align__(16) float  Ws[16 * N];
    int tid = threadIdx.x;
    int tx = tid % NG, ty = tid / NG;
    int base = blockIdx.x * MT;

    unsigned long long acc2[8][8];
    #pragma unroll
    for (int i = 0; i < 8; i++)
        #pragma unroll
        for (int q = 0; q < 8; q++) acc2[i][q] = 0ull;

    for (int kc = 0; kc < K; kc += 16) {
        __syncthreads();
        #pragma unroll
        for (int it = 0; it < (16 * N + T - 1) / T; it++) {
            int i = tid + it * T;
            if ((16 * N) % T == 0 || i < 16 * N) Ws[i] = W[kc * N + i];
        }
        #pragma unroll
        for (int it = 0; it < (MT * 16 + T - 1) / T; it++) {
            int i = tid + it * T;
            if ((MT * 16) % T == 0 || i < MT * 16) {
                int r = i >> 4, k = i & 15, rr = base + r;
                float v = (rr < M) ? X[(size_t)rr * K + kc + k] : 0.f;
                Xd[r * 17 + k] = make_float2(v, v);
            }
        }
        __syncthreads();
        #pragma unroll
        for (int k = 0; k < 16; k++) {
            unsigned long long a[8];
            #pragma unroll
            for (int i = 0; i < 8; i++)
                a[i] = *(const unsigned long long*)&Xd[(ty + RG * i) * 17 + k];
            #pragma unroll
            for (int h = 0; h < 4; h++) {
                ulonglong2 wp = *(const ulonglong2*)&Ws[k * N + tx * 16 + h * 4];
                #pragma unroll
                for (int i = 0; i < 8; i++) {
                    asm("fma.rn.f32x2 %0, %1, %2, %0;"
                        : "+l"(acc2[i][2 * h]) : "l"(a[i]), "l"(wp.x));
                    asm("fma.rn.f32x2 %0, %1, %2, %0;"
                        : "+l"(acc2[i][2 * h + 1]) : "l"(a[i]), "l"(wp.y));
                }
            }
        }
    }
    #pragma unroll
    for (int i = 0; i < 8; i++) {
        int row = base + ty + RG * i;
        if (row >= M) continue;
        #pragma unroll
        for (int h = 0; h < 4; h++) {
            float2 v0 = *(float2*)&acc2[i][2 * h];
            float2 v1 = *(float2*)&acc2[i][2 * h + 1];
            int col = tx * 16 + h * 4;
            float4 v = make_float4(v0.x, v0.y, v1.x, v1.y);
            float4* yp = (float4*)&Y[(size_t)row * N + col];
            if (mode == 2) {
                float4 a = *(const float4*)&addsrc[(size_t)row * N + col];
                float4 b = *(const float4*)&bias[col];
                float4 b2 = *(const float4*)&bias2[col];
                v.x = fmaxf(v.x + a.x + b.x + b2.x, 0.f);
                v.y = fmaxf(v.y + a.y + b.y + b2.y, 0.f);
                v.z = fmaxf(v.z + a.z + b.z + b2.z, 0.f);
                v.w = fmaxf(v.w + a.w + b.w + b2.w, 0.f);
            } else if (mode == 1) {
                float4 o = *yp;
                v.x += o.x; v.y += o.y; v.z += o.z; v.w += o.w;
            }
            *yp = v;
        }
    }
}

// ---------------- fused layer-0 paper GEMM: N=192, 3 destinations ----------------
__global__ void __launch_bounds__(192) k_gemm3(
        const float* __restrict__ X, const float* __restrict__ W,
        const float* __restrict__ dis,
        float* __restrict__ xls, float* __restrict__ P, float* __restrict__ XS, int M) {
    constexpr int K = 128, N = 192, MT = 128, T = 192, RG = 16;
    __shared__ __align__(16) float2 Xd[MT * 17];
    __shared__ __align__(16) float  Ws[16 * N];
    int tid = threadIdx.x;
    int tx = tid % 12, ty = tid / 12;
    int base = blockIdx.x * MT;

    unsigned long long acc2[8][8];
    #pragma unroll
    for (int i = 0; i < 8; i++)
        #pragma unroll
        for (int q = 0; q < 8; q++) acc2[i][q] = 0ull;

    for (int kc = 0; kc < K; kc += 16) {
        __syncthreads();
        #pragma unroll
        for (int it = 0; it < 16; it++) {   // 16*192/192
            int i = tid + it * T;
            Ws[i] = W[kc * N + i];
        }
        #pragma unroll
        for (int it = 0; it < 11; it++) {   // ceil(2048/192)
            int i = tid + it * T;
            if (i < MT * 16) {
                int r = i >> 4, k = i & 15, rr = base + r;
                float v = (rr < M) ? X[(size_t)rr * K + kc + k] : 0.f;
                Xd[r * 17 + k] = make_float2(v, v);
            }
        }
        __syncthreads();
        #pragma unroll
        for (int k = 0; k < 16; k++) {
            unsigned long long a[8];
            #pragma unroll
            for (int i = 0; i < 8; i++)
                a[i] = *(const unsigned long long*)&Xd[(ty + RG * i) * 17 + k];
            #pragma unroll
            for (int h = 0; h < 4; h++) {
                ulonglong2 wp = *(const ulonglong2*)&Ws[k * N + tx * 16 + h * 4];
                #pragma unroll
                for (int i = 0; i < 8; i++) {
                    asm("fma.rn.f32x2 %0, %1, %2, %0;"
                        : "+l"(acc2[i][2 * h]) : "l"(a[i]), "l"(wp.x));
                    asm("fma.rn.f32x2 %0, %1, %2, %0;"
                        : "+l"(acc2[i][2 * h + 1]) : "l"(a[i]), "l"(wp.y));
                }
            }
        }
    }
    #pragma unroll
    for (int i = 0; i < 8; i++) {
        int row = base + ty + RG * i;
        if (row >= M) continue;
        float d = (tx < 4) ? dis[row] : 1.f;
        #pragma unroll
        for (int h = 0; h < 4; h++) {
            float2 v0 = *(float2*)&acc2[i][2 * h];
            float2 v1 = *(float2*)&acc2[i][2 * h + 1];
            float4 v = make_float4(v0.x, v0.y, v1.x, v1.y);
            if (tx < 4) {
                int col = tx * 16 + h * 4;
                v.x *= d; v.y *= d; v.z *= d; v.w *= d;
                *(float4*)&xls[(size_t)row * 64 + col] = v;
            } else if (tx < 8) {
                int col = (tx - 4) * 16 + h * 4;
                *(float4*)&P[(size_t)row * 64 + col] = v;
            } else {
                int col = (tx - 8) * 16 + h * 4;
                *(float4*)&XS[(size_t)row * 64 + col] = v;
            }
        }
    }
}

// ---------------- old small GEMM (kept for the N=32 head) ----------------
template <int K, int N>
__global__ void __launch_bounds__(256) k_gemm2(
        const float* __restrict__ X, const float* __restrict__ W,
        const float* __restrict__ bias, const float* __restrict__ rowscale,
        float* __restrict__ Y, int M, int acc) {
    constexpr int CPT = N / 8;
    constexpr int QP  = CPT / 2;
    __shared__ __align__(16) float  Wc[32 * N];
    __shared__ __align__(16) float2 Xd[128 * 33];
    int tid = threadIdx.x;
    int tx = tid & 7, ty = tid >> 3;
    int base = blockIdx.x * 128;

    unsigned long long accv[4][QP];
    #pragma unroll
    for (int i = 0; i < 4; i++)
        #pragma unroll
        for (int q = 0; q < QP; q++) accv[i][q] = 0ull;

    for (int kc = 0; kc < K; kc += 32) {
        __syncthreads();
        #pragma unroll
        for (int it = 0; it < (32 * N) / 256; it++) {
            int t = tid + it * 256;
            Wc[t] = W[kc * N + t];
        }
        #pragma unroll
        for (int it = 0; it < 16; it++) {
            int idx = tid + it * 256;
            int r = idx >> 5, k = idx & 31;
            int rr = base + r;
            float v = (rr < M) ? X[(size_t)rr * K + kc + k] : 0.f;
            Xd[r * 33 + k] = make_float2(v, v);
        }
        __syncthreads();
        #pragma unroll
        for (int k = 0; k < 32; k++) {
            unsigned long long a[4];
            #pragma unroll
            for (int i = 0; i < 4; i++)
                a[i] = *(const unsigned long long*)&Xd[(ty * 4 + i) * 33 + k];
            #pragma unroll
            for (int h = 0; h < QP / 2; h++) {
                ulonglong2 wp = *(const ulonglong2*)&Wc[k * N + tx * CPT + h * 4];
                #pragma unroll
                for (int i = 0; i < 4; i++) {
                    asm("fma.rn.f32x2 %0, %1, %2, %0;"
                        : "+l"(accv[i][2 * h]) : "l"(a[i]), "l"(wp.x));
                    asm("fma.rn.f32x2 %0, %1, %2, %0;"
                        : "+l"(accv[i][2 * h + 1]) : "l"(a[i]), "l"(wp.y));
                }
            }
        }
    }
    #pragma unroll
    for (int i = 0; i < 4; i++) {
        int row = base + ty * 4 + i;
        if (row >= M) continue;
        float rs = rowscale ? rowscale[row] : 1.f;
        #pragma unroll
        for (int q = 0; q < QP; q++) {
            float2 v = *(float2*)&accv[i][q];
            int col = tx * CPT + 2 * q;
            if (bias) { v.x += bias[col]; v.y += bias[col + 1]; }
            v.x *= rs; v.y *= rs;
            float2* yp = (float2*)&Y[(size_t)row * N + col];
            if (acc) { float2 o = *yp; v.x += o.x; v.y += o.y; }
            *yp = v;
        }
    }
}

// ---------------- host ----------------
static inline int cdiv(long long a, int b) { return (int)((a + b - 1) / b); }

extern "C" void kernel_launch(void* const* d_in, const int* in_sizes, int n_in,
                              void* d_out, int out_size) {
    const float* xp       = (const float*)d_in[0];
    const float* xa       = (const float*)d_in[1];
    const float* gcn_W0   = (const float*)d_in[2];
    const float* gcn_b0   = (const float*)d_in[3];
    const float* sage_Wl0 = (const float*)d_in[4];
    const float* sage_bl0 = (const float*)d_in[5];
    const float* sage_Wr0 = (const float*)d_in[6];
    const float* gat_Ws0  = (const float*)d_in[7];
    const float* gat_Wd0  = (const float*)d_in[8];
    const float* gat_as0  = (const float*)d_in[9];
    const float* gat_ad0  = (const float*)d_in[10];
    const float* gat_b0   = (const float*)d_in[11];
    const float* gat_Ws1  = (const float*)d_in[17];
    const float* gat_Wd1  = (const float*)d_in[18];
    const float* gat_as1  = (const float*)d_in[19];
    const float* gat_ad1  = (const float*)d_in[20];
    const float* gat_b1   = (const float*)d_in[21];
    const float* lin_W    = (const float*)d_in[22];
    const float* lin_b    = (const float*)d_in[23];
    const int* cs = (const int*)d_in[24];
    const int* cd = (const int*)d_in[25];
    const int* ws = (const int*)d_in[26];  // author idx of writes edge
    const int* wd = (const int*)d_in[27];  // paper idx of writes edge
    float* out = (float*)d_out;

    void* p;
    #define SYM(name) cudaGetSymbolAddress(&p, g_##name)
    SYM(xls);  float* xls = (float*)p;
    SYM(P);    float* P   = (float*)p;
    SYM(SA);   float* SA  = (float*)p;
    SYM(XS);   float* XS  = (float*)p;
    SYM(XD);   float* XD  = (float*)p;
    SYM(xp1);  float* xp1 = (float*)p;
    SYM(xa1);  float* xa1 = (float*)p;
    SYM(Wcat); float* Wcat = (float*)p;
    SYM(dis);  float* dis = (float*)p;
    SYM(asrc); float* asrc = (float*)p;
    SYM(adst); float* adst = (float*)p;
    SYM(degC); int* degC = (int*)p;
    SYM(degWp); int* degWp = (int*)p;
    SYM(degWa); int* degWa = (int*)p;
    SYM(offC); int* offC = (int*)p;
    SYM(offWp); int* offWp = (int*)p;
    SYM(offWa); int* offWa = (int*)p;
    SYM(curC); int* curC = (int*)p;
    SYM(curWp); int* curWp = (int*)p;
    SYM(curWa); int* curWa = (int*)p;
    SYM(bsum); int* bsum = (int*)p;
    SYM(csrC); int* csrC = (int*)p;
    SYM(csrWp); int* csrWp = (int*)p;
    SYM(csrWa); int* csrWa = (int*)p;
    #undef SYM

    const int T = 256;

    // ---- CSR build ----
    cudaMemsetAsync(degC, 0, NP * sizeof(int));
    cudaMemsetAsync(degWp, 0, NP * sizeof(int));
    cudaMemsetAsync(degWa, 0, NA * sizeof(int));
    k_count<<<cdiv(EC, T), T>>>(cd, degC, EC);
    k_count<<<cdiv(EW, T), T>>>(wd, degWp, EW);
    k_count<<<cdiv(EW, T), T>>>(ws, degWa, EW);
    k_dis<<<cdiv(NP, T), T>>>(degC, dis, NP);

    k_scan1<<<cdiv(NP, 512), 512>>>(degC, offC, bsum, NP);
    k_scan2<<<1, 512>>>(bsum, cdiv(NP, 512));
    k_scan3<<<cdiv(NP, T), T>>>(offC, curC, bsum, NP);
    k_fill<<<cdiv(EC, T), T>>>(cd, cs, curC, csrC, EC);

    k_scan1<<<cdiv(NP, 512), 512>>>(degWp, offWp, bsum, NP);
    k_scan2<<<1, 512>>>(bsum, cdiv(NP, 512));
    k_scan3<<<cdiv(NP, T), T>>>(offWp, curWp, bsum, NP);
    k_fill<<<cdiv(EW, T), T>>>(wd, ws, curWp, csrWp, EW);

    k_scan1<<<cdiv(NA, 512), 512>>>(degWa, offWa, bsum, NA);
    k_scan2<<<1, 512>>>(bsum, cdiv(NA, 512));
    k_scan3<<<cdiv(NA, T), T>>>(offWa, curWa, bsum, NA);
    k_fill<<<cdiv(EW, T), T>>>(ws, wd, curWa, csrWa, EW);

    // ---- layer 0: fused paper GEMM (gcn | sage_Wr | gat_Ws) ----
    k_wcat<<<cdiv(128 * 192, T), T>>>(gcn_W0, sage_Wr0, gat_Ws0, Wcat);
    k_gemm3<<<cdiv(NP, 128), 192>>>(xp, Wcat, dis, xls, P, XS, NP);

    // ---- layer 0: GCN gather (accumulates into P) ----
    k_gcn_gather<<<cdiv((long long)NP * 32, T), T>>>(offC, csrC, xls, dis, P, NP, EC);

    // ---- layer 0: SAGE; fused combine in GEMM epilogue ----
    k_sage_gather<<<cdiv((long long)NP * 32, T), T>>>(offWp, csrWp, xa, SA, NP, EW);
    k_gemmB<64, 64, 128><<<cdiv(NP, 128), 64>>>(SA, sage_Wl0, gcn_b0, sage_bl0, P, xp1, NP, 2);

    // ---- layer 0: GAT (author<-paper) ----
    k_gemmB<64, 64, 128><<<cdiv(NA, 128), 64>>>(xa, gat_Wd0, nullptr, nullptr, nullptr, XD, NA, 0);
    k_rowdot<<<cdiv((long long)NP * 32, T), T>>>(XS, gat_as0, asrc, NP);
    k_rowdot<<<cdiv((long long)NA * 32, T), T>>>(XD, gat_ad0, adst, NA);
    k_gat_gather<<<cdiv((long long)NA * 32, T), T>>>(offWa, csrWa, asrc, adst, XS,
                                                     gat_b0, xa1, NA, EW);

    // ---- layer 1: only GAT is live ----
    k_gemmB<64, 64, 128><<<cdiv(NP, 128), 64>>>(xp1, gat_Ws1, nullptr, nullptr, nullptr, XS, NP, 0);
    k_gemmB<64, 64, 128><<<cdiv(NA, 128), 64>>>(xa1, gat_Wd1, nullptr, nullptr, nullptr, XD, NA, 0);
    k_rowdot<<<cdiv((long long)NP * 32, T), T>>>(XS, gat_as1, asrc, NP);
    k_rowdot<<<cdiv((long long)NA * 32, T), T>>>(XD, gat_ad1, adst, NA);
    k_gat_gather<<<cdiv((long long)NA * 32, T), T>>>(offWa, csrWa, asrc, adst, XS,
                                                     gat_b1, xa1, NA, EW);

    // ---- output head ----
    k_gemm2<64, 32><<<cdiv(NA, 128), 256>>>(xa1, lin_W, lin_b, nullptr, out, NA, 0);
}